// round 4
// baseline (speedup 1.0000x reference)
#include <cuda_runtime.h>

#define Bt 64
#define NPt 1024
#define Nt 65536
#define Kn 10
#define SLOPEf 0.01f

// ---------------- scratch (device globals; no allocation allowed) ----------------
__device__ __align__(16) float g_f4[Nt * 4];      // xx features
__device__ float g_sq0[Nt];
__device__ float g_u[Nt * 64];                    // xx@(Wtop-Wbot)+b1a
__device__ float g_v[Nt * 64];                    // xx@Wbot
__device__ __align__(16) float g_x1[Nt * 64];
__device__ float g_sq1[Nt];
__device__ int   g_idx1[Nt * Kn];
__device__ int   g_idx2[Nt * Kn];
__device__ __align__(16) float g_P[Nt * 128];     // x1@(W2top-W2bot)+b2
__device__ __align__(16) float g_Q[Nt * 128];     // x1@W2bot
__device__ float g_msum[Bt * 4 * 192];            // per-(batch,sub) partial sums

__device__ __forceinline__ float lrelu(float v) { return v >= 0.f ? v : SLOPEf * v; }

__device__ __forceinline__ unsigned t32(float x) {
    unsigned r;
    asm("cvt.rna.tf32.f32 %0, %1;" : "=r"(r) : "f"(x));
    return r;
}

__device__ __forceinline__ void mma_tf32(float* c, const unsigned* a, unsigned b0, unsigned b1) {
    asm volatile(
        "mma.sync.aligned.m16n8k8.row.col.f32.tf32.tf32.f32 "
        "{%0,%1,%2,%3}, {%4,%5,%6,%7}, {%8,%9}, {%0,%1,%2,%3};"
        : "+f"(c[0]), "+f"(c[1]), "+f"(c[2]), "+f"(c[3])
        : "r"(a[0]), "r"(a[1]), "r"(a[2]), "r"(a[3]), "r"(b0), "r"(b1));
}

// ---------------- K0: per-point precompute (xx, sq0, u, v) ----------------
__global__ void k0_pre(const float* __restrict__ x, const float* __restrict__ pos,
                       const float* __restrict__ w1a, const float* __restrict__ b1a) {
    int gw = (blockIdx.x * blockDim.x + threadIdx.x) >> 5;   // warp per point
    int lane = threadIdx.x & 31;
    int i = gw;
    if (i >= Nt) return;
    float f0 = x[i];
    float f1 = pos[3 * i + 0];
    float f2 = pos[3 * i + 1];
    float f3 = pos[3 * i + 2];
    if (lane == 0) {
        ((float4*)g_f4)[i] = make_float4(f0, f1, f2, f3);
        g_sq0[i] = f0 * f0 + f1 * f1 + f2 * f2 + f3 * f3;
    }
#pragma unroll
    for (int h = 0; h < 2; h++) {
        int o = lane + 32 * h;
        float wt0 = w1a[0 * 64 + o], wt1 = w1a[1 * 64 + o], wt2 = w1a[2 * 64 + o], wt3 = w1a[3 * 64 + o];
        float wb0 = w1a[4 * 64 + o], wb1 = w1a[5 * 64 + o], wb2 = w1a[6 * 64 + o], wb3 = w1a[7 * 64 + o];
        float vv = f0 * wb0 + f1 * wb1 + f2 * wb2 + f3 * wb3;
        float uu = f0 * (wt0 - wb0) + f1 * (wt1 - wb1) + f2 * (wt2 - wb2) + f3 * (wt3 - wb3) + b1a[o];
        g_u[i * 64 + o] = uu;
        g_v[i * 64 + o] = vv;
    }
}

// ---------------- K1: KNN on 4-dim xx (512 blocks x 128 thr for wave balance) ----------------
__global__ void __launch_bounds__(128) k1_knn1() {
    __shared__ float4 sf[NPt];
    __shared__ float  ssq[NPt];
    int b = blockIdx.x >> 3, rb = blockIdx.x & 7;
    int pb = b * NPt;
    for (int t = threadIdx.x; t < NPt; t += 128) {
        sf[t] = ((const float4*)g_f4)[pb + t];
        ssq[t] = g_sq0[pb + t];
    }
    __syncthreads();
    int r = rb * 128 + threadIdx.x;
    int i = pb + r;
    float4 fi = sf[r];
    float bv[Kn]; int bix[Kn];
#pragma unroll
    for (int t = 0; t < Kn; t++) { bv[t] = 3.4e38f; bix[t] = 0; }
    for (int j = 0; j < NPt; j++) {
        float4 fj = sf[j];
        float s = ssq[j] - 2.f * (fi.x * fj.x + fi.y * fj.y + fi.z * fj.z + fi.w * fj.w);
        if (s < bv[Kn - 1]) {
            bv[Kn - 1] = s; bix[Kn - 1] = j;
#pragma unroll
            for (int t = Kn - 1; t > 0; --t) {
                if (bv[t] < bv[t - 1]) {
                    float tv = bv[t]; bv[t] = bv[t - 1]; bv[t - 1] = tv;
                    int ti = bix[t]; bix[t] = bix[t - 1]; bix[t - 1] = ti;
                }
            }
        }
    }
#pragma unroll
    for (int e = 0; e < Kn; e++) g_idx1[i * Kn + e] = pb + bix[e];
}

// ---------------- K2: EdgeConv1 (layers 2+3 per edge, warp-per-point) ----------------
__global__ void __launch_bounds__(256) k2_ec1(const float* __restrict__ w1b, const float* __restrict__ b1b,
                                              const float* __restrict__ w1c, const float* __restrict__ b1c) {
    extern __shared__ float smem[];
    float* ws1b = smem;                  // 4096
    float* ws1c = smem + 4096;           // 4096
    float* hb   = smem + 8192;           // 8 warps * 1280
    int tid = threadIdx.x, lane = tid & 31, w = tid >> 5;
    for (int t = tid; t < 1024; t += 256) {
        ((float4*)ws1b)[t] = ((const float4*)w1b)[t];
        ((float4*)ws1c)[t] = ((const float4*)w1c)[t];
    }
    __syncthreads();
    int i = blockIdx.x * 8 + w;
    float* h1 = hb + w * 1280;
    float* h2 = h1 + 640;
    float u0 = g_u[i * 64 + lane];
    float u1 = g_u[i * 64 + 32 + lane];
    int nbr[Kn];
#pragma unroll
    for (int e = 0; e < Kn; e++) nbr[e] = g_idx1[i * Kn + e];
#pragma unroll
    for (int e = 0; e < Kn; e++) {
        int j = nbr[e];
        h1[e * 64 + lane]      = lrelu(u0 + g_v[j * 64 + lane]);
        h1[e * 64 + 32 + lane] = lrelu(u1 + g_v[j * 64 + 32 + lane]);
    }
    __syncwarp();

    float acc0[Kn], acc1[Kn];
    // layer 2
    {
        float bb0 = b1b[lane], bb1 = b1b[32 + lane];
#pragma unroll
        for (int e = 0; e < Kn; e++) { acc0[e] = bb0; acc1[e] = bb1; }
#pragma unroll 4
        for (int kq = 0; kq < 16; kq++) {
            float w00 = ws1b[(4 * kq + 0) * 64 + lane];
            float w01 = ws1b[(4 * kq + 1) * 64 + lane];
            float w02 = ws1b[(4 * kq + 2) * 64 + lane];
            float w03 = ws1b[(4 * kq + 3) * 64 + lane];
            float w10 = ws1b[(4 * kq + 0) * 64 + 32 + lane];
            float w11 = ws1b[(4 * kq + 1) * 64 + 32 + lane];
            float w12 = ws1b[(4 * kq + 2) * 64 + 32 + lane];
            float w13 = ws1b[(4 * kq + 3) * 64 + 32 + lane];
#pragma unroll
            for (int e = 0; e < Kn; e++) {
                float4 h = *(const float4*)&h1[e * 64 + 4 * kq];
                acc0[e] += h.x * w00 + h.y * w01 + h.z * w02 + h.w * w03;
                acc1[e] += h.x * w10 + h.y * w11 + h.z * w12 + h.w * w13;
            }
        }
#pragma unroll
        for (int e = 0; e < Kn; e++) {
            h2[e * 64 + lane]      = lrelu(acc0[e]);
            h2[e * 64 + 32 + lane] = lrelu(acc1[e]);
        }
    }
    __syncwarp();
    // layer 3 + sum over edges
    {
        float bc0 = b1c[lane], bc1 = b1c[32 + lane];
#pragma unroll
        for (int e = 0; e < Kn; e++) { acc0[e] = bc0; acc1[e] = bc1; }
#pragma unroll 4
        for (int kq = 0; kq < 16; kq++) {
            float w00 = ws1c[(4 * kq + 0) * 64 + lane];
            float w01 = ws1c[(4 * kq + 1) * 64 + lane];
            float w02 = ws1c[(4 * kq + 2) * 64 + lane];
            float w03 = ws1c[(4 * kq + 3) * 64 + lane];
            float w10 = ws1c[(4 * kq + 0) * 64 + 32 + lane];
            float w11 = ws1c[(4 * kq + 1) * 64 + 32 + lane];
            float w12 = ws1c[(4 * kq + 2) * 64 + 32 + lane];
            float w13 = ws1c[(4 * kq + 3) * 64 + 32 + lane];
#pragma unroll
            for (int e = 0; e < Kn; e++) {
                float4 h = *(const float4*)&h2[e * 64 + 4 * kq];
                acc0[e] += h.x * w00 + h.y * w01 + h.z * w02 + h.w * w03;
                acc1[e] += h.x * w10 + h.y * w11 + h.z * w12 + h.w * w13;
            }
        }
    }
    float s0 = 0.f, s1 = 0.f;
#pragma unroll
    for (int e = 0; e < Kn; e++) { s0 += lrelu(acc0[e]); s1 += lrelu(acc1[e]); }
    g_x1[i * 64 + lane] = s0;
    g_x1[i * 64 + 32 + lane] = s1;
    float sq = s0 * s0 + s1 * s1;
#pragma unroll
    for (int off = 16; off; off >>= 1) sq += __shfl_xor_sync(0xffffffffu, sq, off);
    if (lane == 0) g_sq1[i] = sq;
}

// ---------------- K3: KNN on 64-dim x1 via 3xTF32 mma.sync (batched X@X^T) ----------------
// Block: 128 rows of one batch; loops over 8 col-tiles of 128.
// Warp tile: 32 rows x 64 cols (2 m16 x 8 n8 MMAs, K=64 in 8 k-steps).
// hi/lo split: dot = hi@hi + hi@lo + lo@hi (~fp32-exact ranking).
#define STR 76
__global__ void __launch_bounds__(256) k3_knn2() {
    extern __shared__ float smem[];
    float* Ah    = smem;                 // 128*76
    float* Al    = Ah + 128 * STR;
    float* Bh    = Al + 128 * STR;
    float* Bl    = Bh + 128 * STR;
    float* sqc   = Bl + 128 * STR;       // 128
    float* Sbase = sqc + 128;            // 8 * 2080 = 16640

    int tid = threadIdx.x, lane = tid & 31, w = tid >> 5;
    int g = lane >> 2, tig = lane & 3;
    int wy = w >> 1, wx = w & 1;
    int b = blockIdx.x >> 3, rt = blockIdx.x & 7;
    int pb = b * NPt, row0 = rt * 128;

    // stage A tile (block's 128 rows), hi/lo tf32 split
    for (int t = tid; t < 2048; t += 256) {
        int r = t >> 4, q = t & 15;
        float4 v = ((const float4*)g_x1)[(pb + row0 + r) * 16 + q];
        uint4 h = make_uint4(t32(v.x), t32(v.y), t32(v.z), t32(v.w));
        uint4 l = make_uint4(t32(v.x - __uint_as_float(h.x)),
                             t32(v.y - __uint_as_float(h.y)),
                             t32(v.z - __uint_as_float(h.z)),
                             t32(v.w - __uint_as_float(h.w)));
        ((uint4*)(Ah + r * STR))[q] = h;
        ((uint4*)(Al + r * STR))[q] = l;
    }

    float bv[Kn]; int bix[Kn];
#pragma unroll
    for (int t = 0; t < Kn; t++) { bv[t] = 3.4e38f; bix[t] = 0; }

    float* Sw = Sbase + w * 2080;

    for (int ct = 0; ct < 8; ct++) {
        __syncthreads();   // previous tile's B fully consumed
        for (int t = tid; t < 2048; t += 256) {
            int r = t >> 4, q = t & 15;
            float4 v = ((const float4*)g_x1)[(pb + ct * 128 + r) * 16 + q];
            uint4 h = make_uint4(t32(v.x), t32(v.y), t32(v.z), t32(v.w));
            uint4 l = make_uint4(t32(v.x - __uint_as_float(h.x)),
                                 t32(v.y - __uint_as_float(h.y)),
                                 t32(v.z - __uint_as_float(h.z)),
                                 t32(v.w - __uint_as_float(h.w)));
            ((uint4*)(Bh + r * STR))[q] = h;
            ((uint4*)(Bl + r * STR))[q] = l;
        }
        if (tid < 128) sqc[tid] = g_sq1[pb + ct * 128 + tid];
        __syncthreads();

        float acc[2][8][4];
#pragma unroll
        for (int mt = 0; mt < 2; mt++)
#pragma unroll
            for (int nt = 0; nt < 8; nt++)
#pragma unroll
                for (int c = 0; c < 4; c++) acc[mt][nt][c] = 0.f;

#pragma unroll
        for (int kk = 0; kk < 8; kk++) {
            // A fragments: a0=(r,c) a1=(r+8,c) a2=(r,c+4) a3=(r+8,c+4)
            unsigned ah[2][4], al[2][4];
#pragma unroll
            for (int mt = 0; mt < 2; mt++) {
                int ro = (wy * 32 + mt * 16 + g) * STR + kk * 8 + tig;
                ah[mt][0] = __float_as_uint(Ah[ro]);
                ah[mt][1] = __float_as_uint(Ah[ro + 8 * STR]);
                ah[mt][2] = __float_as_uint(Ah[ro + 4]);
                ah[mt][3] = __float_as_uint(Ah[ro + 8 * STR + 4]);
                al[mt][0] = __float_as_uint(Al[ro]);
                al[mt][1] = __float_as_uint(Al[ro + 8 * STR]);
                al[mt][2] = __float_as_uint(Al[ro + 4]);
                al[mt][3] = __float_as_uint(Al[ro + 8 * STR + 4]);
            }
#pragma unroll
            for (int nt = 0; nt < 8; nt++) {
                int bo = (wx * 64 + nt * 8 + g) * STR + kk * 8 + tig;
                unsigned bh0 = __float_as_uint(Bh[bo]);
                unsigned bh1 = __float_as_uint(Bh[bo + 4]);
                unsigned bl0 = __float_as_uint(Bl[bo]);
                unsigned bl1 = __float_as_uint(Bl[bo + 4]);
                mma_tf32(acc[0][nt], ah[0], bl0, bl1);   // hi@lo
                mma_tf32(acc[1][nt], ah[1], bl0, bl1);
                mma_tf32(acc[0][nt], al[0], bh0, bh1);   // lo@hi
                mma_tf32(acc[1][nt], al[1], bh0, bh1);
                mma_tf32(acc[0][nt], ah[0], bh0, bh1);   // hi@hi
                mma_tf32(acc[1][nt], ah[1], bh0, bh1);
            }
        }

        // epilogue: s = sq_j - 2*dot -> per-warp smem score tile
#pragma unroll
        for (int mt = 0; mt < 2; mt++) {
#pragma unroll
            for (int nt = 0; nt < 8; nt++) {
                int rl = mt * 16 + g, c0 = nt * 8 + 2 * tig;
                float sqa = sqc[wx * 64 + c0];
                float sqb = sqc[wx * 64 + c0 + 1];
                Sw[rl * 65 + c0]           = fmaf(-2.f, acc[mt][nt][0], sqa);
                Sw[rl * 65 + c0 + 1]       = fmaf(-2.f, acc[mt][nt][1], sqb);
                Sw[(rl + 8) * 65 + c0]     = fmaf(-2.f, acc[mt][nt][2], sqa);
                Sw[(rl + 8) * 65 + c0 + 1] = fmaf(-2.f, acc[mt][nt][3], sqb);
            }
        }
        __syncwarp();

        // scan: lane owns one of the warp's 32 rows, 64 cols of this tile-half
        int jb = ct * 128 + wx * 64;
        const float* row = Sw + lane * 65;
        for (int c = 0; c < 64; c++) {
            float s = row[c];
            if (s < bv[Kn - 1]) {
                bv[Kn - 1] = s; bix[Kn - 1] = jb + c;
#pragma unroll
                for (int t = Kn - 1; t > 0; --t) {
                    if (bv[t] < bv[t - 1]) {
                        float tv = bv[t]; bv[t] = bv[t - 1]; bv[t - 1] = tv;
                        int ti = bix[t]; bix[t] = bix[t - 1]; bix[t - 1] = ti;
                    }
                }
            }
        }
        __syncwarp();
    }

    // merge the two half-row top-10 lists (wx=0 and wx=1) per row
    __syncthreads();
    float* mv = Sbase;                    // 128*20 floats
    int*   mi = (int*)(Sbase + 2560);     // 128*20 ints
    int r = wy * 32 + lane;
#pragma unroll
    for (int t = 0; t < Kn; t++) {
        mv[r * 20 + wx * 10 + t] = bv[t];
        mi[r * 20 + wx * 10 + t] = bix[t];
    }
    __syncthreads();
    if (tid < 128) {
        const float* v0 = mv + tid * 20;
        const int*   i0 = mi + tid * 20;
        int p = 0, q = 0;
        int gi = (pb + row0 + tid) * Kn;
#pragma unroll
        for (int t = 0; t < Kn; t++) {
            bool take0;
            if (q >= 10) take0 = true;
            else if (p >= 10) take0 = false;
            else take0 = (v0[p] < v0[10 + q]) || (v0[p] == v0[10 + q] && i0[p] < i0[10 + q]);
            int li = take0 ? i0[p] : i0[10 + q];
            if (take0) p++; else q++;
            g_idx2[gi + t] = pb + li;
        }
    }
}

// ---------------- K4: EdgeConv2 per-point P,Q (factored GEMV) ----------------
__global__ void __launch_bounds__(256) k4_pq(const float* __restrict__ w2, const float* __restrict__ b2) {
    extern __shared__ float smem[];
    float* wd  = smem;           // 64*128 : Wtop - Wbot
    float* wbm = smem + 8192;    // 64*128 : Wbot
    float* xb  = smem + 16384;   // 8 warps * 64
    int tid = threadIdx.x, lane = tid & 31, w = tid >> 5;
    for (int t = tid; t < 8192; t += 256) {
        int k = t >> 7, c = t & 127;
        float top = w2[k * 128 + c];
        float bot = w2[(64 + k) * 128 + c];
        wd[t] = top - bot;
        wbm[t] = bot;
    }
    __syncthreads();
    float4 bP = ((const float4*)b2)[lane];
    int base = blockIdx.x * 256 + w * 32;
    for (int pp = 0; pp < 32; pp++) {
        int i = base + pp;
        xb[w * 64 + lane]      = g_x1[i * 64 + lane];
        xb[w * 64 + 32 + lane] = g_x1[i * 64 + 32 + lane];
        __syncwarp();
        float4 accP = bP;
        float4 accQ = make_float4(0.f, 0.f, 0.f, 0.f);
#pragma unroll 4
        for (int kq = 0; kq < 16; kq++) {
            float4 xv = *(const float4*)&xb[w * 64 + 4 * kq];
            float xs[4] = {xv.x, xv.y, xv.z, xv.w};
#pragma unroll
            for (int t = 0; t < 4; t++) {
                float4 wdv = *(const float4*)&wd[(4 * kq + t) * 128 + 4 * lane];
                float4 wbv = *(const float4*)&wbm[(4 * kq + t) * 128 + 4 * lane];
                accP.x += xs[t] * wdv.x; accP.y += xs[t] * wdv.y; accP.z += xs[t] * wdv.z; accP.w += xs[t] * wdv.w;
                accQ.x += xs[t] * wbv.x; accQ.y += xs[t] * wbv.y; accQ.z += xs[t] * wbv.z; accQ.w += xs[t] * wbv.w;
            }
        }
        ((float4*)g_P)[i * 32 + lane] = accP;
        ((float4*)g_Q)[i * 32 + lane] = accQ;
        __syncwarp();
    }
}

// ---------------- K5: EdgeConv2 edge sum + per-(batch,sub) feature sums ----------------
__global__ void __launch_bounds__(256) k5_sum() {
    __shared__ float red[8][192];
    int b = blockIdx.x >> 2, sub = blockIdx.x & 3;
    int lane = threadIdx.x & 31, w = threadIdx.x >> 5;
    int i0 = b * NPt + sub * 256 + w * 32;
    float4 s2 = make_float4(0.f, 0.f, 0.f, 0.f);
    float sx0 = 0.f, sx1 = 0.f;
    for (int pp = 0; pp < 32; pp++) {
        int i = i0 + pp;
        int nbr[Kn];
#pragma unroll
        for (int e = 0; e < Kn; e++) nbr[e] = g_idx2[i * Kn + e];
        float4 Pv = ((const float4*)g_P)[i * 32 + lane];
        float4 a = make_float4(0.f, 0.f, 0.f, 0.f);
#pragma unroll
        for (int e = 0; e < Kn; e++) {
            float4 qv = ((const float4*)g_Q)[nbr[e] * 32 + lane];
            a.x += lrelu(Pv.x + qv.x);
            a.y += lrelu(Pv.y + qv.y);
            a.z += lrelu(Pv.z + qv.z);
            a.w += lrelu(Pv.w + qv.w);
        }
        s2.x += a.x; s2.y += a.y; s2.z += a.z; s2.w += a.w;
        float2 xv = *(const float2*)&g_x1[i * 64 + 2 * lane];
        sx0 += xv.x; sx1 += xv.y;
    }
    red[w][2 * lane] = sx0;
    red[w][2 * lane + 1] = sx1;
    red[w][64 + 4 * lane + 0] = s2.x;
    red[w][64 + 4 * lane + 1] = s2.y;
    red[w][64 + 4 * lane + 2] = s2.z;
    red[w][64 + 4 * lane + 3] = s2.w;
    __syncthreads();
    for (int t = threadIdx.x; t < 192; t += 256) {
        float s = 0.f;
#pragma unroll
        for (int ww = 0; ww < 8; ww++) s += red[ww][t];
        g_msum[blockIdx.x * 192 + t] = s;
    }
}

// ---------------- K7: head MLP (mean -> wl -> wm1 -> wm2 -> wm3) ----------------
__global__ void __launch_bounds__(256) k7_head(const float* __restrict__ wl, const float* __restrict__ bl,
                                               const float* __restrict__ wm1, const float* __restrict__ bm1,
                                               const float* __restrict__ wm2, const float* __restrict__ bm2,
                                               const float* __restrict__ wm3, const float* __restrict__ bm3,
                                               float* __restrict__ out) {
    __shared__ float sm[192];
    __shared__ float h0[1024];
    __shared__ float h1[512];
    __shared__ float h2[256];
    int b = blockIdx.x, tid = threadIdx.x;
    for (int t = tid; t < 192; t += 256) {
        float s = g_msum[(b * 4 + 0) * 192 + t] + g_msum[(b * 4 + 1) * 192 + t]
                + g_msum[(b * 4 + 2) * 192 + t] + g_msum[(b * 4 + 3) * 192 + t];
        sm[t] = s * (1.f / 1024.f);
    }
    __syncthreads();
    for (int o = tid; o < 1024; o += 256) {
        float a0 = 0.f, a1 = 0.f;
        for (int k = 0; k < 192; k += 2) {
            a0 += sm[k] * wl[k * 1024 + o];
            a1 += sm[k + 1] * wl[(k + 1) * 1024 + o];
        }
        h0[o] = a0 + a1 + bl[o];
    }
    __syncthreads();
    for (int o = tid; o < 512; o += 256) {
        float a0 = 0.f, a1 = 0.f, a2 = 0.f, a3 = 0.f;
        for (int k = 0; k < 1024; k += 4) {
            a0 += h0[k] * wm1[k * 512 + o];
            a1 += h0[k + 1] * wm1[(k + 1) * 512 + o];
            a2 += h0[k + 2] * wm1[(k + 2) * 512 + o];
            a3 += h0[k + 3] * wm1[(k + 3) * 512 + o];
        }
        h1[o] = lrelu(a0 + a1 + a2 + a3 + bm1[o]);
    }
    __syncthreads();
    if (tid < 256) {
        float a0 = 0.f, a1 = 0.f, a2 = 0.f, a3 = 0.f;
        for (int k = 0; k < 512; k += 4) {
            a0 += h1[k] * wm2[k * 256 + tid];
            a1 += h1[k + 1] * wm2[(k + 1) * 256 + tid];
            a2 += h1[k + 2] * wm2[(k + 2) * 256 + tid];
            a3 += h1[k + 3] * wm2[(k + 3) * 256 + tid];
        }
        h2[tid] = lrelu(a0 + a1 + a2 + a3 + bm2[tid]);
    }
    __syncthreads();
    if (tid < 3) {
        float a = bm3[tid];
        for (int k = 0; k < 256; k++) a += h2[k] * wm3[k * 3 + tid];
        out[b * 3 + tid] = a;
    }
}

// ---------------- launch ----------------
extern "C" void kernel_launch(void* const* d_in, const int* in_sizes, int n_in,
                              void* d_out, int out_size) {
    const float* x   = (const float*)d_in[0];
    const float* pos = (const float*)d_in[1];
    // d_in[2] = batch (int32) — layout is deterministic (b = i / 1024), unused
    const float* w1a = (const float*)d_in[3];
    const float* b1a = (const float*)d_in[4];
    const float* w1b = (const float*)d_in[5];
    const float* b1b = (const float*)d_in[6];
    const float* w1c = (const float*)d_in[7];
    const float* b1c = (const float*)d_in[8];
    const float* w2  = (const float*)d_in[9];
    const float* b2  = (const float*)d_in[10];
    const float* wl  = (const float*)d_in[11];
    const float* bl  = (const float*)d_in[12];
    const float* wm1 = (const float*)d_in[13];
    const float* bm1 = (const float*)d_in[14];
    const float* wm2 = (const float*)d_in[15];
    const float* bm2 = (const float*)d_in[16];
    const float* wm3 = (const float*)d_in[17];
    const float* bm3 = (const float*)d_in[18];
    float* out = (float*)d_out;

    // k3 smem: 4*128*76 + 128 + 8*2080 floats = 222720 bytes
    const int K3_SMEM = (4 * 128 * STR + 128 + 8 * 2080) * 4;
    cudaFuncSetAttribute(k2_ec1,  cudaFuncAttributeMaxDynamicSharedMemorySize, 73728);
    cudaFuncSetAttribute(k3_knn2, cudaFuncAttributeMaxDynamicSharedMemorySize, K3_SMEM);
    cudaFuncSetAttribute(k4_pq,   cudaFuncAttributeMaxDynamicSharedMemorySize, 67584);

    k0_pre<<<Nt / 8, 256>>>(x, pos, w1a, b1a);
    k1_knn1<<<Bt * 8, 128>>>();
    k2_ec1<<<Nt / 8, 256, 73728>>>(w1b, b1b, w1c, b1c);
    k3_knn2<<<Bt * 8, 256, K3_SMEM>>>();
    k4_pq<<<Nt / 256, 256, 67584>>>(w2, b2);
    k5_sum<<<Bt * 4, 256>>>();
    k7_head<<<Bt, 256>>>(wl, bl, wm1, bm1, wm2, bm2, wm3, bm3, out);
}

// round 5
// speedup vs baseline: 1.1670x; 1.1670x over previous
#include <cuda_runtime.h>
#include <cuda_fp16.h>

#define Bt 64
#define NPt 1024
#define Nt 65536
#define Kn 10
#define SLOPEf 0.01f

// ---------------- scratch (device globals; no allocation allowed) ----------------
__device__ __align__(16) float g_f4[Nt * 4];      // xx features
__device__ float g_sq0[Nt];
__device__ float g_u[Nt * 64];                    // xx@(Wtop-Wbot)+b1a
__device__ float g_v[Nt * 64];                    // xx@Wbot
__device__ __align__(16) float g_x1[Nt * 64];
__device__ __align__(16) __half g_x1h[Nt * 64];   // fp16 hi part of x1
__device__ __align__(16) __half g_x1l[Nt * 64];   // fp16 lo part of x1
__device__ float g_sq1[Nt];
__device__ int   g_idx1[Nt * Kn];
__device__ int   g_idx2[Nt * Kn];
__device__ __align__(16) float g_P[Nt * 128];     // x1@(W2top-W2bot)+b2
__device__ __align__(16) float g_Q[Nt * 128];     // x1@W2bot
__device__ float g_msum[Bt * 4 * 192];            // per-(batch,sub) partial sums

__device__ __forceinline__ float lrelu(float v) { return v >= 0.f ? v : SLOPEf * v; }

__device__ __forceinline__ void ldsm4(unsigned& r0, unsigned& r1, unsigned& r2, unsigned& r3,
                                      unsigned saddr) {
    asm volatile("ldmatrix.sync.aligned.m8n8.x4.shared.b16 {%0,%1,%2,%3}, [%4];"
                 : "=r"(r0), "=r"(r1), "=r"(r2), "=r"(r3) : "r"(saddr));
}

__device__ __forceinline__ void mma16816(float* c, const unsigned* a, unsigned b0, unsigned b1) {
    asm volatile(
        "mma.sync.aligned.m16n8k16.row.col.f32.f16.f16.f32 "
        "{%0,%1,%2,%3}, {%4,%5,%6,%7}, {%8,%9}, {%0,%1,%2,%3};"
        : "+f"(c[0]), "+f"(c[1]), "+f"(c[2]), "+f"(c[3])
        : "r"(a[0]), "r"(a[1]), "r"(a[2]), "r"(a[3]), "r"(b0), "r"(b1));
}

#define INS(BV, BI, S, J)                                                        \
    if ((S) < BV[Kn - 1]) {                                                      \
        BV[Kn - 1] = (S); BI[Kn - 1] = (J);                                      \
        _Pragma("unroll")                                                        \
        for (int _t = Kn - 1; _t > 0; --_t) {                                    \
            if (BV[_t] < BV[_t - 1]) {                                           \
                float _tv = BV[_t]; BV[_t] = BV[_t - 1]; BV[_t - 1] = _tv;       \
                int _ti = BI[_t]; BI[_t] = BI[_t - 1]; BI[_t - 1] = _ti;         \
            }                                                                    \
        }                                                                        \
    }

// ---------------- K0: per-point precompute (xx, sq0, u, v) ----------------
__global__ void k0_pre(const float* __restrict__ x, const float* __restrict__ pos,
                       const float* __restrict__ w1a, const float* __restrict__ b1a) {
    int gw = (blockIdx.x * blockDim.x + threadIdx.x) >> 5;   // warp per point
    int lane = threadIdx.x & 31;
    int i = gw;
    if (i >= Nt) return;
    float f0 = x[i];
    float f1 = pos[3 * i + 0];
    float f2 = pos[3 * i + 1];
    float f3 = pos[3 * i + 2];
    if (lane == 0) {
        ((float4*)g_f4)[i] = make_float4(f0, f1, f2, f3);
        g_sq0[i] = f0 * f0 + f1 * f1 + f2 * f2 + f3 * f3;
    }
#pragma unroll
    for (int h = 0; h < 2; h++) {
        int o = lane + 32 * h;
        float wt0 = w1a[0 * 64 + o], wt1 = w1a[1 * 64 + o], wt2 = w1a[2 * 64 + o], wt3 = w1a[3 * 64 + o];
        float wb0 = w1a[4 * 64 + o], wb1 = w1a[5 * 64 + o], wb2 = w1a[6 * 64 + o], wb3 = w1a[7 * 64 + o];
        float vv = f0 * wb0 + f1 * wb1 + f2 * wb2 + f3 * wb3;
        float uu = f0 * (wt0 - wb0) + f1 * (wt1 - wb1) + f2 * (wt2 - wb2) + f3 * (wt3 - wb3) + b1a[o];
        g_u[i * 64 + o] = uu;
        g_v[i * 64 + o] = vv;
    }
}

// ---------------- K1: KNN on 4-dim xx ----------------
__global__ void __launch_bounds__(128) k1_knn1() {
    __shared__ float4 sf[NPt];
    __shared__ float  ssq[NPt];
    int b = blockIdx.x >> 3, rb = blockIdx.x & 7;
    int pb = b * NPt;
    for (int t = threadIdx.x; t < NPt; t += 128) {
        sf[t] = ((const float4*)g_f4)[pb + t];
        ssq[t] = g_sq0[pb + t];
    }
    __syncthreads();
    int r = rb * 128 + threadIdx.x;
    int i = pb + r;
    float4 fi = sf[r];
    float bv[Kn]; int bix[Kn];
#pragma unroll
    for (int t = 0; t < Kn; t++) { bv[t] = 3.4e38f; bix[t] = 0; }
    for (int j = 0; j < NPt; j++) {
        float4 fj = sf[j];
        float s = ssq[j] - 2.f * (fi.x * fj.x + fi.y * fj.y + fi.z * fj.z + fi.w * fj.w);
        INS(bv, bix, s, j)
    }
#pragma unroll
    for (int e = 0; e < Kn; e++) g_idx1[i * Kn + e] = pb + bix[e];
}

// ---------------- K2: EdgeConv1 (layers 2+3 per edge, warp-per-point) ----------------
__global__ void __launch_bounds__(256) k2_ec1(const float* __restrict__ w1b, const float* __restrict__ b1b,
                                              const float* __restrict__ w1c, const float* __restrict__ b1c) {
    extern __shared__ float smem[];
    float* ws1b = smem;                  // 4096
    float* ws1c = smem + 4096;           // 4096
    float* hb   = smem + 8192;           // 8 warps * 1280
    int tid = threadIdx.x, lane = tid & 31, w = tid >> 5;
    for (int t = tid; t < 1024; t += 256) {
        ((float4*)ws1b)[t] = ((const float4*)w1b)[t];
        ((float4*)ws1c)[t] = ((const float4*)w1c)[t];
    }
    __syncthreads();
    int i = blockIdx.x * 8 + w;
    float* h1 = hb + w * 1280;
    float* h2 = h1 + 640;
    float u0 = g_u[i * 64 + lane];
    float u1 = g_u[i * 64 + 32 + lane];
    int nbr[Kn];
#pragma unroll
    for (int e = 0; e < Kn; e++) nbr[e] = g_idx1[i * Kn + e];
#pragma unroll
    for (int e = 0; e < Kn; e++) {
        int j = nbr[e];
        h1[e * 64 + lane]      = lrelu(u0 + g_v[j * 64 + lane]);
        h1[e * 64 + 32 + lane] = lrelu(u1 + g_v[j * 64 + 32 + lane]);
    }
    __syncwarp();

    float acc0[Kn], acc1[Kn];
    // layer 2
    {
        float bb0 = b1b[lane], bb1 = b1b[32 + lane];
#pragma unroll
        for (int e = 0; e < Kn; e++) { acc0[e] = bb0; acc1[e] = bb1; }
#pragma unroll 4
        for (int kq = 0; kq < 16; kq++) {
            float w00 = ws1b[(4 * kq + 0) * 64 + lane];
            float w01 = ws1b[(4 * kq + 1) * 64 + lane];
            float w02 = ws1b[(4 * kq + 2) * 64 + lane];
            float w03 = ws1b[(4 * kq + 3) * 64 + lane];
            float w10 = ws1b[(4 * kq + 0) * 64 + 32 + lane];
            float w11 = ws1b[(4 * kq + 1) * 64 + 32 + lane];
            float w12 = ws1b[(4 * kq + 2) * 64 + 32 + lane];
            float w13 = ws1b[(4 * kq + 3) * 64 + 32 + lane];
#pragma unroll
            for (int e = 0; e < Kn; e++) {
                float4 h = *(const float4*)&h1[e * 64 + 4 * kq];
                acc0[e] += h.x * w00 + h.y * w01 + h.z * w02 + h.w * w03;
                acc1[e] += h.x * w10 + h.y * w11 + h.z * w12 + h.w * w13;
            }
        }
#pragma unroll
        for (int e = 0; e < Kn; e++) {
            h2[e * 64 + lane]      = lrelu(acc0[e]);
            h2[e * 64 + 32 + lane] = lrelu(acc1[e]);
        }
    }
    __syncwarp();
    // layer 3 + sum over edges
    {
        float bc0 = b1c[lane], bc1 = b1c[32 + lane];
#pragma unroll
        for (int e = 0; e < Kn; e++) { acc0[e] = bc0; acc1[e] = bc1; }
#pragma unroll 4
        for (int kq = 0; kq < 16; kq++) {
            float w00 = ws1c[(4 * kq + 0) * 64 + lane];
            float w01 = ws1c[(4 * kq + 1) * 64 + lane];
            float w02 = ws1c[(4 * kq + 2) * 64 + lane];
            float w03 = ws1c[(4 * kq + 3) * 64 + lane];
            float w10 = ws1c[(4 * kq + 0) * 64 + 32 + lane];
            float w11 = ws1c[(4 * kq + 1) * 64 + 32 + lane];
            float w12 = ws1c[(4 * kq + 2) * 64 + 32 + lane];
            float w13 = ws1c[(4 * kq + 3) * 64 + 32 + lane];
#pragma unroll
            for (int e = 0; e < Kn; e++) {
                float4 h = *(const float4*)&h2[e * 64 + 4 * kq];
                acc0[e] += h.x * w00 + h.y * w01 + h.z * w02 + h.w * w03;
                acc1[e] += h.x * w10 + h.y * w11 + h.z * w12 + h.w * w13;
            }
        }
    }
    float s0 = 0.f, s1 = 0.f;
#pragma unroll
    for (int e = 0; e < Kn; e++) { s0 += lrelu(acc0[e]); s1 += lrelu(acc1[e]); }
    g_x1[i * 64 + lane] = s0;
    g_x1[i * 64 + 32 + lane] = s1;
    // fp16 hi/lo split for the MMA-KNN
    __half h0 = __float2half_rn(s0);
    __half l0 = __float2half_rn(s0 - __half2float(h0));
    __half h1v = __float2half_rn(s1);
    __half l1v = __float2half_rn(s1 - __half2float(h1v));
    g_x1h[i * 64 + lane] = h0;       g_x1l[i * 64 + lane] = l0;
    g_x1h[i * 64 + 32 + lane] = h1v; g_x1l[i * 64 + 32 + lane] = l1v;
    float sq = s0 * s0 + s1 * s1;
#pragma unroll
    for (int off = 16; off; off >>= 1) sq += __shfl_xor_sync(0xffffffffu, sq, off);
    if (lane == 0) g_sq1[i] = sq;
}

// ---------------- K3: KNN on 64-dim x1 via fp16-split m16n8k16 MMA + ldmatrix ----------------
// Block: 256 thr (8 warps), 128 rows of one batch; 16 B-tiles of 64 cols.
// Warp: 16 rows x 64 cols (8 n8 MMAs x 3 split terms per k16-step, 4 k-steps).
// Top-10 kept in registers per lane (quad-lane owns 1/4 of each row's cols),
// 4-way merge per row at the end. smem ~55KB -> 2 blocks/SM.
#define HSTR 72
__global__ void __launch_bounds__(256, 2) k3_knn2() {
    extern __shared__ __align__(16) char smraw[];
    __half* Ah = (__half*)smraw;                 // 128*72 halves
    __half* Al = Ah + 128 * HSTR;
    __half* Bh = Al + 128 * HSTR;                // 64*72
    __half* Bl = Bh + 64 * HSTR;
    float*  ssq = (float*)(Bl + 64 * HSTR);      // 64 floats

    int tid = threadIdx.x, lane = tid & 31, w = tid >> 5;
    int g = lane >> 2, tig = lane & 3;
    int b = blockIdx.x >> 3, rt = blockIdx.x & 7;
    int pb = b * NPt, row0 = rt * 128;

    // stage A (128 rows x 64 halves, hi & lo)
    for (int t = tid; t < 1024; t += 256) {
        int r = t >> 3, q = t & 7;
        ((uint4*)(Ah + r * HSTR))[q] = ((const uint4*)(g_x1h + (pb + row0 + r) * 64))[q];
        ((uint4*)(Al + r * HSTR))[q] = ((const uint4*)(g_x1l + (pb + row0 + r) * 64))[q];
    }

    float bv0[Kn], bv1[Kn]; int bi0[Kn], bi1[Kn];
#pragma unroll
    for (int t = 0; t < Kn; t++) { bv0[t] = 3.4e38f; bi0[t] = 0; bv1[t] = 3.4e38f; bi1[t] = 0; }

    // ldmatrix shared addresses
    unsigned sAh = (unsigned)__cvta_generic_to_shared(Ah);
    unsigned sAl = (unsigned)__cvta_generic_to_shared(Al);
    unsigned sBh = (unsigned)__cvta_generic_to_shared(Bh);
    unsigned sBl = (unsigned)__cvta_generic_to_shared(Bl);
    int arow = w * 16 + (lane & 15);
    int akoff = (lane >> 4) * 8;
    unsigned aAh = sAh + (arow * HSTR + akoff) * 2;
    unsigned aAl = sAl + (arow * HSTR + akoff) * 2;
    int bsub = lane >> 3, brr = lane & 7;
    int bn = (bsub >> 1) * 8 + brr;
    int bko = (bsub & 1) * 8;
    unsigned aBh = sBh + (bn * HSTR + bko) * 2;
    unsigned aBl = sBl + (bn * HSTR + bko) * 2;

    for (int ct = 0; ct < 16; ct++) {
        __syncthreads();   // previous tile fully consumed
        for (int t = tid; t < 512; t += 256) {
            int r = t >> 3, q = t & 7;
            ((uint4*)(Bh + r * HSTR))[q] = ((const uint4*)(g_x1h + (pb + ct * 64 + r) * 64))[q];
            ((uint4*)(Bl + r * HSTR))[q] = ((const uint4*)(g_x1l + (pb + ct * 64 + r) * 64))[q];
        }
        if (tid < 64) ssq[tid] = g_sq1[pb + ct * 64 + tid];
        __syncthreads();

        float acc[8][4];
#pragma unroll
        for (int nt = 0; nt < 8; nt++)
#pragma unroll
            for (int c = 0; c < 4; c++) acc[nt][c] = 0.f;

#pragma unroll
        for (int kk = 0; kk < 4; kk++) {
            unsigned ah[4], al[4];
            ldsm4(ah[0], ah[1], ah[2], ah[3], aAh + kk * 32);
            ldsm4(al[0], al[1], al[2], al[3], aAl + kk * 32);
#pragma unroll
            for (int p = 0; p < 4; p++) {
                unsigned bh0, bh1, bh2, bh3, bl0, bl1, bl2, bl3;
                unsigned boff = (unsigned)(p * 16 * HSTR * 2 + kk * 32);
                ldsm4(bh0, bh1, bh2, bh3, aBh + boff);
                ldsm4(bl0, bl1, bl2, bl3, aBl + boff);
                mma16816(acc[2 * p],     ah, bh0, bh1);   // hi@hi
                mma16816(acc[2 * p],     ah, bl0, bl1);   // hi@lo
                mma16816(acc[2 * p],     al, bh0, bh1);   // lo@hi
                mma16816(acc[2 * p + 1], ah, bh2, bh3);
                mma16816(acc[2 * p + 1], ah, bl2, bl3);
                mma16816(acc[2 * p + 1], al, bh2, bh3);
            }
        }

        // scan from registers: row g -> bv0, row g+8 -> bv1
        int jb = ct * 64;
#pragma unroll
        for (int nt = 0; nt < 8; nt++) {
            int c0 = nt * 8 + 2 * tig;
            float sq0 = ssq[c0], sq1 = ssq[c0 + 1];
            float s;
            s = fmaf(-2.f, acc[nt][0], sq0); INS(bv0, bi0, s, jb + c0)
            s = fmaf(-2.f, acc[nt][1], sq1); INS(bv0, bi0, s, jb + c0 + 1)
            s = fmaf(-2.f, acc[nt][2], sq0); INS(bv1, bi1, s, jb + c0)
            s = fmaf(-2.f, acc[nt][3], sq1); INS(bv1, bi1, s, jb + c0 + 1)
        }
    }

    // dump per-lane lists and 4-way merge per row
    __syncthreads();
    float* mv = (float*)smraw;            // [128][4][10] floats
    int*   mi = ((int*)smraw) + 5120;     // [128][4][10] ints
    int r0 = w * 16 + g;
#pragma unroll
    for (int t = 0; t < Kn; t++) {
        mv[(r0 * 4 + tig) * 10 + t] = bv0[t];
        mi[(r0 * 4 + tig) * 10 + t] = bi0[t];
        mv[((r0 + 8) * 4 + tig) * 10 + t] = bv1[t];
        mi[((r0 + 8) * 4 + tig) * 10 + t] = bi1[t];
    }
    __syncthreads();
    if (tid < 128) {
        const float* V = mv + tid * 40;
        const int*   I = mi + tid * 40;
        int p0 = 0, p1 = 0, p2 = 0, p3 = 0;
        int gi = (pb + row0 + tid) * Kn;
#pragma unroll
        for (int t = 0; t < Kn; t++) {
            float v0 = V[p0], v1 = V[10 + p1], v2 = V[20 + p2], v3 = V[30 + p3];
            int   i0 = I[p0], i1 = I[10 + p1], i2 = I[20 + p2], i3 = I[30 + p3];
            // lexicographic (val, idx) min of 4 heads
            float va; int ia; bool a01 = (v0 < v1) || (v0 == v1 && i0 < i1);
            va = a01 ? v0 : v1; ia = a01 ? i0 : i1;
            float vb; int ib; bool b23 = (v2 < v3) || (v2 == v3 && i2 < i3);
            vb = b23 ? v2 : v3; ib = b23 ? i2 : i3;
            bool ab = (va < vb) || (va == vb && ia < ib);
            int li = ab ? ia : ib;
            if (ab) { if (a01) p0++; else p1++; }
            else    { if (b23) p2++; else p3++; }
            g_idx2[gi + t] = pb + li;
        }
    }
}

// ---------------- K4: EdgeConv2 per-point P,Q (factored GEMV) ----------------
__global__ void __launch_bounds__(256) k4_pq(const float* __restrict__ w2, const float* __restrict__ b2) {
    extern __shared__ float smem[];
    float* wd  = smem;           // 64*128 : Wtop - Wbot
    float* wbm = smem + 8192;    // 64*128 : Wbot
    float* xb  = smem + 16384;   // 8 warps * 64
    int tid = threadIdx.x, lane = tid & 31, w = tid >> 5;
    for (int t = tid; t < 8192; t += 256) {
        int k = t >> 7, c = t & 127;
        float top = w2[k * 128 + c];
        float bot = w2[(64 + k) * 128 + c];
        wd[t] = top - bot;
        wbm[t] = bot;
    }
    __syncthreads();
    float4 bP = ((const float4*)b2)[lane];
    int base = blockIdx.x * 256 + w * 32;
    for (int pp = 0; pp < 32; pp++) {
        int i = base + pp;
        xb[w * 64 + lane]      = g_x1[i * 64 + lane];
        xb[w * 64 + 32 + lane] = g_x1[i * 64 + 32 + lane];
        __syncwarp();
        float4 accP = bP;
        float4 accQ = make_float4(0.f, 0.f, 0.f, 0.f);
#pragma unroll 4
        for (int kq = 0; kq < 16; kq++) {
            float4 xv = *(const float4*)&xb[w * 64 + 4 * kq];
            float xs[4] = {xv.x, xv.y, xv.z, xv.w};
#pragma unroll
            for (int t = 0; t < 4; t++) {
                float4 wdv = *(const float4*)&wd[(4 * kq + t) * 128 + 4 * lane];
                float4 wbv = *(const float4*)&wbm[(4 * kq + t) * 128 + 4 * lane];
                accP.x += xs[t] * wdv.x; accP.y += xs[t] * wdv.y; accP.z += xs[t] * wdv.z; accP.w += xs[t] * wdv.w;
                accQ.x += xs[t] * wbv.x; accQ.y += xs[t] * wbv.y; accQ.z += xs[t] * wbv.z; accQ.w += xs[t] * wbv.w;
            }
        }
        ((float4*)g_P)[i * 32 + lane] = accP;
        ((float4*)g_Q)[i * 32 + lane] = accQ;
        __syncwarp();
    }
}

// ---------------- K5: EdgeConv2 edge sum + per-(batch,sub) feature sums ----------------
__global__ void __launch_bounds__(256) k5_sum() {
    __shared__ float red[8][192];
    int b = blockIdx.x >> 2, sub = blockIdx.x & 3;
    int lane = threadIdx.x & 31, w = threadIdx.x >> 5;
    int i0 = b * NPt + sub * 256 + w * 32;
    float4 s2 = make_float4(0.f, 0.f, 0.f, 0.f);
    float sx0 = 0.f, sx1 = 0.f;
    for (int pp = 0; pp < 32; pp++) {
        int i = i0 + pp;
        int nbr[Kn];
#pragma unroll
        for (int e = 0; e < Kn; e++) nbr[e] = g_idx2[i * Kn + e];
        float4 Pv = ((const float4*)g_P)[i * 32 + lane];
        float4 a = make_float4(0.f, 0.f, 0.f, 0.f);
#pragma unroll
        for (int e = 0; e < Kn; e++) {
            float4 qv = ((const float4*)g_Q)[nbr[e] * 32 + lane];
            a.x += lrelu(Pv.x + qv.x);
            a.y += lrelu(Pv.y + qv.y);
            a.z += lrelu(Pv.z + qv.z);
            a.w += lrelu(Pv.w + qv.w);
        }
        s2.x += a.x; s2.y += a.y; s2.z += a.z; s2.w += a.w;
        float2 xv = *(const float2*)&g_x1[i * 64 + 2 * lane];
        sx0 += xv.x; sx1 += xv.y;
    }
    red[w][2 * lane] = sx0;
    red[w][2 * lane + 1] = sx1;
    red[w][64 + 4 * lane + 0] = s2.x;
    red[w][64 + 4 * lane + 1] = s2.y;
    red[w][64 + 4 * lane + 2] = s2.z;
    red[w][64 + 4 * lane + 3] = s2.w;
    __syncthreads();
    for (int t = threadIdx.x; t < 192; t += 256) {
        float s = 0.f;
#pragma unroll
        for (int ww = 0; ww < 8; ww++) s += red[ww][t];
        g_msum[blockIdx.x * 192 + t] = s;
    }
}

// ---------------- K7: head MLP (mean -> wl -> wm1 -> wm2 -> wm3) ----------------
__global__ void __launch_bounds__(256) k7_head(const float* __restrict__ wl, const float* __restrict__ bl,
                                               const float* __restrict__ wm1, const float* __restrict__ bm1,
                                               const float* __restrict__ wm2, const float* __restrict__ bm2,
                                               const float* __restrict__ wm3, const float* __restrict__ bm3,
                                               float* __restrict__ out) {
    __shared__ float sm[192];
    __shared__ float h0[1024];
    __shared__ float h1[512];
    __shared__ float h2[256];
    int b = blockIdx.x, tid = threadIdx.x;
    for (int t = tid; t < 192; t += 256) {
        float s = g_msum[(b * 4 + 0) * 192 + t] + g_msum[(b * 4 + 1) * 192 + t]
                + g_msum[(b * 4 + 2) * 192 + t] + g_msum[(b * 4 + 3) * 192 + t];
        sm[t] = s * (1.f / 1024.f);
    }
    __syncthreads();
    for (int o = tid; o < 1024; o += 256) {
        float a0 = 0.f, a1 = 0.f;
        for (int k = 0; k < 192; k += 2) {
            a0 += sm[k] * wl[k * 1024 + o];
            a1 += sm[k + 1] * wl[(k + 1) * 1024 + o];
        }
        h0[o] = a0 + a1 + bl[o];
    }
    __syncthreads();
    for (int o = tid; o < 512; o += 256) {
        float a0 = 0.f, a1 = 0.f, a2 = 0.f, a3 = 0.f;
        for (int k = 0; k < 1024; k += 4) {
            a0 += h0[k] * wm1[k * 512 + o];
            a1 += h0[k + 1] * wm1[(k + 1) * 512 + o];
            a2 += h0[k + 2] * wm1[(k + 2) * 512 + o];
            a3 += h0[k + 3] * wm1[(k + 3) * 512 + o];
        }
        h1[o] = lrelu(a0 + a1 + a2 + a3 + bm1[o]);
    }
    __syncthreads();
    if (tid < 256) {
        float a0 = 0.f, a1 = 0.f, a2 = 0.f, a3 = 0.f;
        for (int k = 0; k < 512; k += 4) {
            a0 += h1[k] * wm2[k * 256 + tid];
            a1 += h1[k + 1] * wm2[(k + 1) * 256 + tid];
            a2 += h1[k + 2] * wm2[(k + 2) * 256 + tid];
            a3 += h1[k + 3] * wm2[(k + 3) * 256 + tid];
        }
        h2[tid] = lrelu(a0 + a1 + a2 + a3 + bm2[tid]);
    }
    __syncthreads();
    if (tid < 3) {
        float a = bm3[tid];
        for (int k = 0; k < 256; k++) a += h2[k] * wm3[k * 3 + tid];
        out[b * 3 + tid] = a;
    }
}

// ---------------- launch ----------------
extern "C" void kernel_launch(void* const* d_in, const int* in_sizes, int n_in,
                              void* d_out, int out_size) {
    const float* x   = (const float*)d_in[0];
    const float* pos = (const float*)d_in[1];
    // d_in[2] = batch (int32) — layout is deterministic (b = i / 1024), unused
    const float* w1a = (const float*)d_in[3];
    const float* b1a = (const float*)d_in[4];
    const float* w1b = (const float*)d_in[5];
    const float* b1b = (const float*)d_in[6];
    const float* w1c = (const float*)d_in[7];
    const float* b1c = (const float*)d_in[8];
    const float* w2  = (const float*)d_in[9];
    const float* b2  = (const float*)d_in[10];
    const float* wl  = (const float*)d_in[11];
    const float* bl  = (const float*)d_in[12];
    const float* wm1 = (const float*)d_in[13];
    const float* bm1 = (const float*)d_in[14];
    const float* wm2 = (const float*)d_in[15];
    const float* bm2 = (const float*)d_in[16];
    const float* wm3 = (const float*)d_in[17];
    const float* bm3 = (const float*)d_in[18];
    float* out = (float*)d_out;

    // k3 smem: (128+64)*72 halves *2 arrays + 64 floats = 55552 bytes
    const int K3_SMEM = (128 * HSTR * 2 + 64 * HSTR * 2) * 2 + 64 * 4;
    cudaFuncSetAttribute(k2_ec1,  cudaFuncAttributeMaxDynamicSharedMemorySize, 73728);
    cudaFuncSetAttribute(k3_knn2, cudaFuncAttributeMaxDynamicSharedMemorySize, K3_SMEM);
    cudaFuncSetAttribute(k4_pq,   cudaFuncAttributeMaxDynamicSharedMemorySize, 67584);

    k0_pre<<<Nt / 8, 256>>>(x, pos, w1a, b1a);
    k1_knn1<<<Bt * 8, 128>>>();
    k2_ec1<<<Nt / 8, 256, 73728>>>(w1b, b1b, w1c, b1c);
    k3_knn2<<<Bt * 8, 256, K3_SMEM>>>();
    k4_pq<<<Nt / 256, 256, 67584>>>(w2, b2);
    k5_sum<<<Bt * 4, 256>>>();
    k7_head<<<Bt, 256>>>(wl, bl, wm1, bm1, wm2, bm2, wm3, bm3, out);
}

// round 6
// speedup vs baseline: 1.2504x; 1.0714x over previous
#include <cuda_runtime.h>
#include <cuda_fp16.h>

#define Bt 64
#define NPt 1024
#define Nt 65536
#define Kn 10
#define SLOPEf 0.01f

// ---------------- scratch (device globals; no allocation allowed) ----------------
__device__ __align__(16) float g_f4[Nt * 4];      // xx features
__device__ float g_sq0[Nt];
__device__ float g_u[Nt * 64];                    // xx@(Wtop-Wbot)+b1a
__device__ float g_v[Nt * 64];                    // xx@Wbot
__device__ __align__(16) float g_x1[Nt * 64];
__device__ __align__(16) __half g_x1h[Nt * 64];   // fp16 hi part of x1
__device__ __align__(16) __half g_x1l[Nt * 64];   // fp16 lo part of x1
__device__ float g_sq1[Nt];
__device__ int   g_idx1[Nt * Kn];
__device__ int   g_idx2[Nt * Kn];
__device__ __align__(16) float g_P[Nt * 128];     // x1@(W2top-W2bot)+b2
__device__ __align__(16) float g_Q[Nt * 128];     // x1@W2bot
__device__ float g_msum[Bt * 4 * 192];            // per-(batch,sub) partial sums

__device__ __forceinline__ float lrelu(float v) { return v >= 0.f ? v : SLOPEf * v; }

__device__ __forceinline__ void ldsm4(unsigned& r0, unsigned& r1, unsigned& r2, unsigned& r3,
                                      unsigned saddr) {
    asm volatile("ldmatrix.sync.aligned.m8n8.x4.shared.b16 {%0,%1,%2,%3}, [%4];"
                 : "=r"(r0), "=r"(r1), "=r"(r2), "=r"(r3) : "r"(saddr) : "memory");
}

__device__ __forceinline__ void mma16816(float* c, const unsigned* a, unsigned b0, unsigned b1) {
    asm volatile(
        "mma.sync.aligned.m16n8k16.row.col.f32.f16.f16.f32 "
        "{%0,%1,%2,%3}, {%4,%5,%6,%7}, {%8,%9}, {%0,%1,%2,%3};"
        : "+f"(c[0]), "+f"(c[1]), "+f"(c[2]), "+f"(c[3])
        : "r"(a[0]), "r"(a[1]), "r"(a[2]), "r"(a[3]), "r"(b0), "r"(b1));
}

#define INS(BV, BI, S, J)                                                        \
    if ((S) < BV[Kn - 1]) {                                                      \
        BV[Kn - 1] = (S); BI[Kn - 1] = (J);                                      \
        _Pragma("unroll")                                                        \
        for (int _t = Kn - 1; _t > 0; --_t) {                                    \
            if (BV[_t] < BV[_t - 1]) {                                           \
                float _tv = BV[_t]; BV[_t] = BV[_t - 1]; BV[_t - 1] = _tv;       \
                int _ti = BI[_t]; BI[_t] = BI[_t - 1]; BI[_t - 1] = _ti;         \
            }                                                                    \
        }                                                                        \
    }

// ---------------- K0: per-point precompute (xx, sq0, u, v) ----------------
__global__ void k0_pre(const float* __restrict__ x, const float* __restrict__ pos,
                       const float* __restrict__ w1a, const float* __restrict__ b1a) {
    int gw = (blockIdx.x * blockDim.x + threadIdx.x) >> 5;   // warp per point
    int lane = threadIdx.x & 31;
    int i = gw;
    if (i >= Nt) return;
    float f0 = x[i];
    float f1 = pos[3 * i + 0];
    float f2 = pos[3 * i + 1];
    float f3 = pos[3 * i + 2];
    if (lane == 0) {
        ((float4*)g_f4)[i] = make_float4(f0, f1, f2, f3);
        g_sq0[i] = f0 * f0 + f1 * f1 + f2 * f2 + f3 * f3;
    }
#pragma unroll
    for (int h = 0; h < 2; h++) {
        int o = lane + 32 * h;
        float wt0 = w1a[0 * 64 + o], wt1 = w1a[1 * 64 + o], wt2 = w1a[2 * 64 + o], wt3 = w1a[3 * 64 + o];
        float wb0 = w1a[4 * 64 + o], wb1 = w1a[5 * 64 + o], wb2 = w1a[6 * 64 + o], wb3 = w1a[7 * 64 + o];
        float vv = f0 * wb0 + f1 * wb1 + f2 * wb2 + f3 * wb3;
        float uu = f0 * (wt0 - wb0) + f1 * (wt1 - wb1) + f2 * (wt2 - wb2) + f3 * (wt3 - wb3) + b1a[o];
        g_u[i * 64 + o] = uu;
        g_v[i * 64 + o] = vv;
    }
}

// ---------------- K1: KNN on 4-dim xx ----------------
__global__ void __launch_bounds__(128) k1_knn1() {
    __shared__ float4 sf[NPt];
    __shared__ float  ssq[NPt];
    int b = blockIdx.x >> 3, rb = blockIdx.x & 7;
    int pb = b * NPt;
    for (int t = threadIdx.x; t < NPt; t += 128) {
        sf[t] = ((const float4*)g_f4)[pb + t];
        ssq[t] = g_sq0[pb + t];
    }
    __syncthreads();
    int r = rb * 128 + threadIdx.x;
    int i = pb + r;
    float4 fi = sf[r];
    float bv[Kn]; int bix[Kn];
#pragma unroll
    for (int t = 0; t < Kn; t++) { bv[t] = 3.4e38f; bix[t] = 0; }
    for (int j = 0; j < NPt; j++) {
        float4 fj = sf[j];
        float s = ssq[j] - 2.f * (fi.x * fj.x + fi.y * fj.y + fi.z * fj.z + fi.w * fj.w);
        INS(bv, bix, s, j)
    }
#pragma unroll
    for (int e = 0; e < Kn; e++) g_idx1[i * Kn + e] = pb + bix[e];
}

// ---------------- K2: EdgeConv1 layers 2+3 via fp16-split MMA (warp = 1 point) ----------------
// Point's 10 edges padded to an m16 tile (rows 10-15 = copy of row 0, excluded from sum).
// Per layer: A = H (16x64 hi/lo), B = Wt[o][k] (64x64 hi/lo); 8 n-tiles x 4 k-steps x 3 terms.
#define WSTR 72
__global__ void __launch_bounds__(256, 2) k2_ec1(const float* __restrict__ w1b, const float* __restrict__ b1b,
                                                 const float* __restrict__ w1c, const float* __restrict__ b1c) {
    extern __shared__ __align__(16) char smraw[];
    __half* Wbh = (__half*)smraw;                 // 64*72 halves each
    __half* Wbl = Wbh + 64 * WSTR;
    __half* Wch = Wbl + 64 * WSTR;
    __half* Wcl = Wch + 64 * WSTR;
    float*  sbb = (float*)(Wcl + 64 * WSTR);      // 64
    float*  sbc = sbb + 64;                       // 64
    __half* Hbase = (__half*)(sbc + 64);          // 8 warps * 2*16*72 halves

    int tid = threadIdx.x, lane = tid & 31, w = tid >> 5;
    int g = lane >> 2, tig = lane & 3;

    // stage transposed + hi/lo split weights, biases
    for (int t = tid; t < 4096; t += 256) {
        int o = t & 63, k = t >> 6;               // w[k*64+o] read coalesced
        float vb = w1b[t];
        __half hb = __float2half_rn(vb);
        Wbh[o * WSTR + k] = hb;
        Wbl[o * WSTR + k] = __float2half_rn(vb - __half2float(hb));
        float vc = w1c[t];
        __half hc = __float2half_rn(vc);
        Wch[o * WSTR + k] = hc;
        Wcl[o * WSTR + k] = __float2half_rn(vc - __half2float(hc));
    }
    if (tid < 64) { sbb[tid] = b1b[tid]; sbc[tid] = b1c[tid]; }
    __syncthreads();

    __half* Hh = Hbase + w * (2 * 16 * WSTR);
    __half* Hl = Hh + 16 * WSTR;

    unsigned sHh = (unsigned)__cvta_generic_to_shared(Hh);
    unsigned sHl = (unsigned)__cvta_generic_to_shared(Hl);
    unsigned aAh = sHh + ((lane & 15) * WSTR + (lane >> 4) * 8) * 2;
    unsigned aAl = sHl + ((lane & 15) * WSTR + (lane >> 4) * 8) * 2;
    int bsub = lane >> 3, brr = lane & 7;
    int bn = (bsub >> 1) * 8 + brr;
    int bko = (bsub & 1) * 8;
    unsigned bbase = (unsigned)((bn * WSTR + bko) * 2);
    unsigned aWbh = (unsigned)__cvta_generic_to_shared(Wbh) + bbase;
    unsigned aWbl = (unsigned)__cvta_generic_to_shared(Wbl) + bbase;
    unsigned aWch = (unsigned)__cvta_generic_to_shared(Wch) + bbase;
    unsigned aWcl = (unsigned)__cvta_generic_to_shared(Wcl) + bbase;

    for (int p = 0; p < 4; p++) {
        int i = blockIdx.x * 32 + w * 4 + p;

        // ---- build H1 (16 x 64, hi/lo) ----
        float2 u = *(const float2*)&g_u[i * 64 + 2 * lane];
        __half2 r0h, r0l;
#pragma unroll
        for (int e = 0; e < Kn; e++) {
            int j = g_idx1[i * Kn + e];
            float2 v = *(const float2*)&g_v[j * 64 + 2 * lane];
            float h0 = lrelu(u.x + v.x), h1 = lrelu(u.y + v.y);
            __half hh0 = __float2half_rn(h0), hh1 = __float2half_rn(h1);
            __half ll0 = __float2half_rn(h0 - __half2float(hh0));
            __half ll1 = __float2half_rn(h1 - __half2float(hh1));
            __half2 ph = __halves2half2(hh0, hh1), pl = __halves2half2(ll0, ll1);
            *(__half2*)(Hh + e * WSTR + 2 * lane) = ph;
            *(__half2*)(Hl + e * WSTR + 2 * lane) = pl;
            if (e == 0) { r0h = ph; r0l = pl; }
        }
#pragma unroll
        for (int e = Kn; e < 16; e++) {
            *(__half2*)(Hh + e * WSTR + 2 * lane) = r0h;
            *(__half2*)(Hl + e * WSTR + 2 * lane) = r0l;
        }
        __syncwarp();

        float acc[8][4];

        // ---- layer 2 ----
#pragma unroll
        for (int nt = 0; nt < 8; nt++)
#pragma unroll
            for (int c = 0; c < 4; c++) acc[nt][c] = 0.f;
#pragma unroll
        for (int kk = 0; kk < 4; kk++) {
            unsigned ah[4], al[4];
            ldsm4(ah[0], ah[1], ah[2], ah[3], aAh + kk * 32);
            ldsm4(al[0], al[1], al[2], al[3], aAl + kk * 32);
#pragma unroll
            for (int pg = 0; pg < 4; pg++) {
                unsigned boff = (unsigned)(pg * 16 * WSTR * 2 + kk * 32);
                unsigned bh0, bh1, bh2, bh3, bl0, bl1, bl2, bl3;
                ldsm4(bh0, bh1, bh2, bh3, aWbh + boff);
                ldsm4(bl0, bl1, bl2, bl3, aWbl + boff);
                mma16816(acc[2 * pg],     ah, bh0, bh1);
                mma16816(acc[2 * pg],     ah, bl0, bl1);
                mma16816(acc[2 * pg],     al, bh0, bh1);
                mma16816(acc[2 * pg + 1], ah, bh2, bh3);
                mma16816(acc[2 * pg + 1], ah, bl2, bl3);
                mma16816(acc[2 * pg + 1], al, bh2, bh3);
            }
        }
        __syncwarp();

        // bias + lrelu + split, store H2 over H1
#pragma unroll
        for (int nt = 0; nt < 8; nt++) {
            int c0 = nt * 8 + 2 * tig;
            float b0v = sbb[c0], b1v = sbb[c0 + 1];
            float v00 = lrelu(acc[nt][0] + b0v), v01 = lrelu(acc[nt][1] + b1v);
            float v10 = lrelu(acc[nt][2] + b0v), v11 = lrelu(acc[nt][3] + b1v);
            __half h00 = __float2half_rn(v00), h01 = __float2half_rn(v01);
            __half h10 = __float2half_rn(v10), h11 = __float2half_rn(v11);
            *(__half2*)(Hh + g * WSTR + c0)       = __halves2half2(h00, h01);
            *(__half2*)(Hh + (g + 8) * WSTR + c0) = __halves2half2(h10, h11);
            *(__half2*)(Hl + g * WSTR + c0)       = __halves2half2(__float2half_rn(v00 - __half2float(h00)),
                                                                   __float2half_rn(v01 - __half2float(h01)));
            *(__half2*)(Hl + (g + 8) * WSTR + c0) = __halves2half2(__float2half_rn(v10 - __half2float(h10)),
                                                                   __float2half_rn(v11 - __half2float(h11)));
        }
        __syncwarp();

        // ---- layer 3 ----
#pragma unroll
        for (int nt = 0; nt < 8; nt++)
#pragma unroll
            for (int c = 0; c < 4; c++) acc[nt][c] = 0.f;
#pragma unroll
        for (int kk = 0; kk < 4; kk++) {
            unsigned ah[4], al[4];
            ldsm4(ah[0], ah[1], ah[2], ah[3], aAh + kk * 32);
            ldsm4(al[0], al[1], al[2], al[3], aAl + kk * 32);
#pragma unroll
            for (int pg = 0; pg < 4; pg++) {
                unsigned boff = (unsigned)(pg * 16 * WSTR * 2 + kk * 32);
                unsigned bh0, bh1, bh2, bh3, bl0, bl1, bl2, bl3;
                ldsm4(bh0, bh1, bh2, bh3, aWch + boff);
                ldsm4(bl0, bl1, bl2, bl3, aWcl + boff);
                mma16816(acc[2 * pg],     ah, bh0, bh1);
                mma16816(acc[2 * pg],     ah, bl0, bl1);
                mma16816(acc[2 * pg],     al, bh0, bh1);
                mma16816(acc[2 * pg + 1], ah, bh2, bh3);
                mma16816(acc[2 * pg + 1], ah, bl2, bl3);
                mma16816(acc[2 * pg + 1], al, bh2, bh3);
            }
        }
        __syncwarp();

        // bias + lrelu + sum over edges 0..9 (rows 0-7 = g rows; rows 8,9 = g+8 with g<2)
        float cs0[8], cs1[8];
#pragma unroll
        for (int nt = 0; nt < 8; nt++) {
            int c0 = nt * 8 + 2 * tig;
            float b0v = sbc[c0], b1v = sbc[c0 + 1];
            float t0 = lrelu(acc[nt][0] + b0v);
            float t1 = lrelu(acc[nt][1] + b1v);
            if (g < 2) {
                t0 += lrelu(acc[nt][2] + b0v);
                t1 += lrelu(acc[nt][3] + b1v);
            }
#pragma unroll
            for (int off = 4; off < 32; off <<= 1) {
                t0 += __shfl_xor_sync(0xffffffffu, t0, off);
                t1 += __shfl_xor_sync(0xffffffffu, t1, off);
            }
            cs0[nt] = t0; cs1[nt] = t1;
        }
        // sq reduction (all lanes hold full column sums for their tig's columns)
        float sq = 0.f;
#pragma unroll
        for (int nt = 0; nt < 8; nt++) sq += cs0[nt] * cs0[nt] + cs1[nt] * cs1[nt];
        sq += __shfl_xor_sync(0xffffffffu, sq, 1);
        sq += __shfl_xor_sync(0xffffffffu, sq, 2);
        if (lane < 4) {
#pragma unroll
            for (int nt = 0; nt < 8; nt++) {
                int c0 = nt * 8 + 2 * lane;
                *(float2*)&g_x1[i * 64 + c0] = make_float2(cs0[nt], cs1[nt]);
                __half hh0 = __float2half_rn(cs0[nt]), hh1 = __float2half_rn(cs1[nt]);
                *(__half2*)(g_x1h + i * 64 + c0) = __halves2half2(hh0, hh1);
                *(__half2*)(g_x1l + i * 64 + c0) =
                    __halves2half2(__float2half_rn(cs0[nt] - __half2float(hh0)),
                                   __float2half_rn(cs1[nt] - __half2float(hh1)));
            }
            if (lane == 0) g_sq1[i] = sq;
        }
        __syncwarp();
    }
}

// ---------------- K3: KNN on 64-dim x1 via fp16-split m16n8k16 MMA + ldmatrix ----------------
#define HSTR 72
__global__ void __launch_bounds__(256, 2) k3_knn2() {
    extern __shared__ __align__(16) char smraw[];
    __half* Ah = (__half*)smraw;                 // 128*72 halves
    __half* Al = Ah + 128 * HSTR;
    __half* Bh = Al + 128 * HSTR;                // 64*72
    __half* Bl = Bh + 64 * HSTR;
    float*  ssq = (float*)(Bl + 64 * HSTR);      // 64 floats

    int tid = threadIdx.x, lane = tid & 31, w = tid >> 5;
    int g = lane >> 2, tig = lane & 3;
    int b = blockIdx.x >> 3, rt = blockIdx.x & 7;
    int pb = b * NPt, row0 = rt * 128;

    // stage A (128 rows x 64 halves, hi & lo)
    for (int t = tid; t < 1024; t += 256) {
        int r = t >> 3, q = t & 7;
        ((uint4*)(Ah + r * HSTR))[q] = ((const uint4*)(g_x1h + (pb + row0 + r) * 64))[q];
        ((uint4*)(Al + r * HSTR))[q] = ((const uint4*)(g_x1l + (pb + row0 + r) * 64))[q];
    }

    float bv0[Kn], bv1[Kn]; int bi0[Kn], bi1[Kn];
#pragma unroll
    for (int t = 0; t < Kn; t++) { bv0[t] = 3.4e38f; bi0[t] = 0; bv1[t] = 3.4e38f; bi1[t] = 0; }

    unsigned sAh = (unsigned)__cvta_generic_to_shared(Ah);
    unsigned sAl = (unsigned)__cvta_generic_to_shared(Al);
    unsigned sBh = (unsigned)__cvta_generic_to_shared(Bh);
    unsigned sBl = (unsigned)__cvta_generic_to_shared(Bl);
    int arow = w * 16 + (lane & 15);
    int akoff = (lane >> 4) * 8;
    unsigned aAh = sAh + (arow * HSTR + akoff) * 2;
    unsigned aAl = sAl + (arow * HSTR + akoff) * 2;
    int bsub = lane >> 3, brr = lane & 7;
    int bn = (bsub >> 1) * 8 + brr;
    int bko = (bsub & 1) * 8;
    unsigned aBh = sBh + (bn * HSTR + bko) * 2;
    unsigned aBl = sBl + (bn * HSTR + bko) * 2;

    for (int ct = 0; ct < 16; ct++) {
        __syncthreads();
        for (int t = tid; t < 512; t += 256) {
            int r = t >> 3, q = t & 7;
            ((uint4*)(Bh + r * HSTR))[q] = ((const uint4*)(g_x1h + (pb + ct * 64 + r) * 64))[q];
            ((uint4*)(Bl + r * HSTR))[q] = ((const uint4*)(g_x1l + (pb + ct * 64 + r) * 64))[q];
        }
        if (tid < 64) ssq[tid] = g_sq1[pb + ct * 64 + tid];
        __syncthreads();

        float acc[8][4];
#pragma unroll
        for (int nt = 0; nt < 8; nt++)
#pragma unroll
            for (int c = 0; c < 4; c++) acc[nt][c] = 0.f;

#pragma unroll
        for (int kk = 0; kk < 4; kk++) {
            unsigned ah[4], al[4];
            ldsm4(ah[0], ah[1], ah[2], ah[3], aAh + kk * 32);
            ldsm4(al[0], al[1], al[2], al[3], aAl + kk * 32);
#pragma unroll
            for (int p = 0; p < 4; p++) {
                unsigned bh0, bh1, bh2, bh3, bl0, bl1, bl2, bl3;
                unsigned boff = (unsigned)(p * 16 * HSTR * 2 + kk * 32);
                ldsm4(bh0, bh1, bh2, bh3, aBh + boff);
                ldsm4(bl0, bl1, bl2, bl3, aBl + boff);
                mma16816(acc[2 * p],     ah, bh0, bh1);
                mma16816(acc[2 * p],     ah, bl0, bl1);
                mma16816(acc[2 * p],     al, bh0, bh1);
                mma16816(acc[2 * p + 1], ah, bh2, bh3);
                mma16816(acc[2 * p + 1], ah, bl2, bl3);
                mma16816(acc[2 * p + 1], al, bh2, bh3);
            }
        }

        int jb = ct * 64;
#pragma unroll
        for (int nt = 0; nt < 8; nt++) {
            int c0 = nt * 8 + 2 * tig;
            float sq0 = ssq[c0], sq1 = ssq[c0 + 1];
            float s;
            s = fmaf(-2.f, acc[nt][0], sq0); INS(bv0, bi0, s, jb + c0)
            s = fmaf(-2.f, acc[nt][1], sq1); INS(bv0, bi0, s, jb + c0 + 1)
            s = fmaf(-2.f, acc[nt][2], sq0); INS(bv1, bi1, s, jb + c0)
            s = fmaf(-2.f, acc[nt][3], sq1); INS(bv1, bi1, s, jb + c0 + 1)
        }
    }

    __syncthreads();
    float* mv = (float*)smraw;            // [128][4][10] floats
    int*   mi = ((int*)smraw) + 5120;     // [128][4][10] ints
    int r0 = w * 16 + g;
#pragma unroll
    for (int t = 0; t < Kn; t++) {
        mv[(r0 * 4 + tig) * 10 + t] = bv0[t];
        mi[(r0 * 4 + tig) * 10 + t] = bi0[t];
        mv[((r0 + 8) * 4 + tig) * 10 + t] = bv1[t];
        mi[((r0 + 8) * 4 + tig) * 10 + t] = bi1[t];
    }
    __syncthreads();
    if (tid < 128) {
        const float* V = mv + tid * 40;
        const int*   I = mi + tid * 40;
        int p0 = 0, p1 = 0, p2 = 0, p3 = 0;
        int gi = (pb + row0 + tid) * Kn;
#pragma unroll
        for (int t = 0; t < Kn; t++) {
            float v0 = V[p0], v1 = V[10 + p1], v2 = V[20 + p2], v3 = V[30 + p3];
            int   i0 = I[p0], i1 = I[10 + p1], i2 = I[20 + p2], i3 = I[30 + p3];
            float va; int ia; bool a01 = (v0 < v1) || (v0 == v1 && i0 < i1);
            va = a01 ? v0 : v1; ia = a01 ? i0 : i1;
            float vb; int ib; bool b23 = (v2 < v3) || (v2 == v3 && i2 < i3);
            vb = b23 ? v2 : v3; ib = b23 ? i2 : i3;
            bool ab = (va < vb) || (va == vb && ia < ib);
            int li = ab ? ia : ib;
            if (ab) { if (a01) p0++; else p1++; }
            else    { if (b23) p2++; else p3++; }
            g_idx2[gi + t] = pb + li;
        }
    }
}

// ---------------- K4: EdgeConv2 per-point P,Q (factored GEMV) ----------------
__global__ void __launch_bounds__(256) k4_pq(const float* __restrict__ w2, const float* __restrict__ b2) {
    extern __shared__ float smem[];
    float* wd  = smem;           // 64*128 : Wtop - Wbot
    float* wbm = smem + 8192;    // 64*128 : Wbot
    float* xb  = smem + 16384;   // 8 warps * 64
    int tid = threadIdx.x, lane = tid & 31, w = tid >> 5;
    for (int t = tid; t < 8192; t += 256) {
        int k = t >> 7, c = t & 127;
        float top = w2[k * 128 + c];
        float bot = w2[(64 + k) * 128 + c];
        wd[t] = top - bot;
        wbm[t] = bot;
    }
    __syncthreads();
    float4 bP = ((const float4*)b2)[lane];
    int base = blockIdx.x * 256 + w * 32;
    for (int pp = 0; pp < 32; pp++) {
        int i = base + pp;
        xb[w * 64 + lane]      = g_x1[i * 64 + lane];
        xb[w * 64 + 32 + lane] = g_x1[i * 64 + 32 + lane];
        __syncwarp();
        float4 accP = bP;
        float4 accQ = make_float4(0.f, 0.f, 0.f, 0.f);
#pragma unroll 4
        for (int kq = 0; kq < 16; kq++) {
            float4 xv = *(const float4*)&xb[w * 64 + 4 * kq];
            float xs[4] = {xv.x, xv.y, xv.z, xv.w};
#pragma unroll
            for (int t = 0; t < 4; t++) {
                float4 wdv = *(const float4*)&wd[(4 * kq + t) * 128 + 4 * lane];
                float4 wbv = *(const float4*)&wbm[(4 * kq + t) * 128 + 4 * lane];
                accP.x += xs[t] * wdv.x; accP.y += xs[t] * wdv.y; accP.z += xs[t] * wdv.z; accP.w += xs[t] * wdv.w;
                accQ.x += xs[t] * wbv.x; accQ.y += xs[t] * wbv.y; accQ.z += xs[t] * wbv.z; accQ.w += xs[t] * wbv.w;
            }
        }
        ((float4*)g_P)[i * 32 + lane] = accP;
        ((float4*)g_Q)[i * 32 + lane] = accQ;
        __syncwarp();
    }
}

// ---------------- K5: EdgeConv2 edge sum + per-(batch,sub) feature sums ----------------
__global__ void __launch_bounds__(256) k5_sum() {
    __shared__ float red[8][192];
    int b = blockIdx.x >> 2, sub = blockIdx.x & 3;
    int lane = threadIdx.x & 31, w = threadIdx.x >> 5;
    int i0 = b * NPt + sub * 256 + w * 32;
    float4 s2 = make_float4(0.f, 0.f, 0.f, 0.f);
    float sx0 = 0.f, sx1 = 0.f;
    for (int pp = 0; pp < 32; pp++) {
        int i = i0 + pp;
        int nbr[Kn];
#pragma unroll
        for (int e = 0; e < Kn; e++) nbr[e] = g_idx2[i * Kn + e];
        float4 Pv = ((const float4*)g_P)[i * 32 + lane];
        float4 a = make_float4(0.f, 0.f, 0.f, 0.f);
#pragma unroll
        for (int e = 0; e < Kn; e++) {
            float4 qv = ((const float4*)g_Q)[nbr[e] * 32 + lane];
            a.x += lrelu(Pv.x + qv.x);
            a.y += lrelu(Pv.y + qv.y);
            a.z += lrelu(Pv.z + qv.z);
            a.w += lrelu(Pv.w + qv.w);
        }
        s2.x += a.x; s2.y += a.y; s2.z += a.z; s2.w += a.w;
        float2 xv = *(const float2*)&g_x1[i * 64 + 2 * lane];
        sx0 += xv.x; sx1 += xv.y;
    }
    red[w][2 * lane] = sx0;
    red[w][2 * lane + 1] = sx1;
    red[w][64 + 4 * lane + 0] = s2.x;
    red[w][64 + 4 * lane + 1] = s2.y;
    red[w][64 + 4 * lane + 2] = s2.z;
    red[w][64 + 4 * lane + 3] = s2.w;
    __syncthreads();
    for (int t = threadIdx.x; t < 192; t += 256) {
        float s = 0.f;
#pragma unroll
        for (int ww = 0; ww < 8; ww++) s += red[ww][t];
        g_msum[blockIdx.x * 192 + t] = s;
    }
}

// ---------------- K7: head MLP (mean -> wl -> wm1 -> wm2 -> wm3) ----------------
__global__ void __launch_bounds__(256) k7_head(const float* __restrict__ wl, const float* __restrict__ bl,
                                               const float* __restrict__ wm1, const float* __restrict__ bm1,
                                               const float* __restrict__ wm2, const float* __restrict__ bm2,
                                               const float* __restrict__ wm3, const float* __restrict__ bm3,
                                               float* __restrict__ out) {
    __shared__ float sm[192];
    __shared__ float h0[1024];
    __shared__ float h1[512];
    __shared__ float h2[256];
    int b = blockIdx.x, tid = threadIdx.x;
    for (int t = tid; t < 192; t += 256) {
        float s = g_msum[(b * 4 + 0) * 192 + t] + g_msum[(b * 4 + 1) * 192 + t]
                + g_msum[(b * 4 + 2) * 192 + t] + g_msum[(b * 4 + 3) * 192 + t];
        sm[t] = s * (1.f / 1024.f);
    }
    __syncthreads();
    for (int o = tid; o < 1024; o += 256) {
        float a0 = 0.f, a1 = 0.f;
        for (int k = 0; k < 192; k += 2) {
            a0 += sm[k] * wl[k * 1024 + o];
            a1 += sm[k + 1] * wl[(k + 1) * 1024 + o];
        }
        h0[o] = a0 + a1 + bl[o];
    }
    __syncthreads();
    for (int o = tid; o < 512; o += 256) {
        float a0 = 0.f, a1 = 0.f, a2 = 0.f, a3 = 0.f;
        for (int k = 0; k < 1024; k += 4) {
            a0 += h0[k] * wm1[k * 512 + o];
            a1 += h0[k + 1] * wm1[(k + 1) * 512 + o];
            a2 += h0[k + 2] * wm1[(k + 2) * 512 + o];
            a3 += h0[k + 3] * wm1[(k + 3) * 512 + o];
        }
        h1[o] = lrelu(a0 + a1 + a2 + a3 + bm1[o]);
    }
    __syncthreads();
    if (tid < 256) {
        float a0 = 0.f, a1 = 0.f, a2 = 0.f, a3 = 0.f;
        for (int k = 0; k < 512; k += 4) {
            a0 += h1[k] * wm2[k * 256 + tid];
            a1 += h1[k + 1] * wm2[(k + 1) * 256 + tid];
            a2 += h1[k + 2] * wm2[(k + 2) * 256 + tid];
            a3 += h1[k + 3] * wm2[(k + 3) * 256 + tid];
        }
        h2[tid] = lrelu(a0 + a1 + a2 + a3 + bm2[tid]);
    }
    __syncthreads();
    if (tid < 3) {
        float a = bm3[tid];
        for (int k = 0; k < 256; k++) a += h2[k] * wm3[k * 3 + tid];
        out[b * 3 + tid] = a;
    }
}

// ---------------- launch ----------------
extern "C" void kernel_launch(void* const* d_in, const int* in_sizes, int n_in,
                              void* d_out, int out_size) {
    const float* x   = (const float*)d_in[0];
    const float* pos = (const float*)d_in[1];
    // d_in[2] = batch (int32) — layout is deterministic (b = i / 1024), unused
    const float* w1a = (const float*)d_in[3];
    const float* b1a = (const float*)d_in[4];
    const float* w1b = (const float*)d_in[5];
    const float* b1b = (const float*)d_in[6];
    const float* w1c = (const float*)d_in[7];
    const float* b1c = (const float*)d_in[8];
    const float* w2  = (const float*)d_in[9];
    const float* b2  = (const float*)d_in[10];
    const float* wl  = (const float*)d_in[11];
    const float* bl  = (const float*)d_in[12];
    const float* wm1 = (const float*)d_in[13];
    const float* bm1 = (const float*)d_in[14];
    const float* wm2 = (const float*)d_in[15];
    const float* bm2 = (const float*)d_in[16];
    const float* wm3 = (const float*)d_in[17];
    const float* bm3 = (const float*)d_in[18];
    float* out = (float*)d_out;

    // k2 smem: 4 weight arrays (64*72 halves) + 128 bias floats + 8 warps * 2 * 16*72 halves
    const int K2_SMEM = 4 * 64 * WSTR * 2 + 128 * 4 + 8 * 2 * 16 * WSTR * 2;
    // k3 smem: (128+64)*72 halves *2 arrays + 64 floats
    const int K3_SMEM = (128 * HSTR * 2 + 64 * HSTR * 2) * 2 + 64 * 4;
    cudaFuncSetAttribute(k2_ec1,  cudaFuncAttributeMaxDynamicSharedMemorySize, K2_SMEM);
    cudaFuncSetAttribute(k3_knn2, cudaFuncAttributeMaxDynamicSharedMemorySize, K3_SMEM);
    cudaFuncSetAttribute(k4_pq,   cudaFuncAttributeMaxDynamicSharedMemorySize, 67584);

    k0_pre<<<Nt / 8, 256>>>(x, pos, w1a, b1a);
    k1_knn1<<<Bt * 8, 128>>>();
    k2_ec1<<<Nt / 32, 256, K2_SMEM>>>(w1b, b1b, w1c, b1c);
    k3_knn2<<<Bt * 8, 256, K3_SMEM>>>();
    k4_pq<<<Nt / 256, 256, 67584>>>(w2, b2);
    k5_sum<<<Bt * 4, 256>>>();
    k7_head<<<Bt, 256>>>(wl, bl, wm1, bm1, wm2, bm2, wm3, bm3, out);
}